// round 16
// baseline (speedup 1.0000x reference)
#include <cuda_runtime.h>
#include <math.h>
#include <stdint.h>

// Problem constants
#define BB 2
#define LL 1024
#define HH 256
#define NHEAD 8
#define DHEAD 32
#define FFD 1024
#define NLAYER 2
#define RELN 100
#define EPSLN 1e-5f
// 1/sqrt(32) * log2(e)  (exp done in base 2)
#define QSCALE (0.17677669529663687f * 1.4426950408889634f)

#define ROWS (BB*LL)          // 2048

// ---------------- scratch (static device memory; no allocations allowed) ----
__device__ float g_qb[ROWS*HH];
__device__ float g_kb[ROWS*HH];
__device__ float g_vb[ROWS*HH];
__device__ float g_ab[ROWS*HH];
__device__ float g_yb[ROWS*HH];
__device__ float g_xb[ROWS*HH];
__device__ float g_fb[ROWS*FFD];
__device__ int   g_rm[BB*LL*LL];   // packed rel | mask<<31

__device__ __forceinline__ float ex2f(float x) {
    float y;
    asm("ex2.approx.ftz.f32 %0, %1;" : "=f"(y) : "f"(x));
    return y;
}

__device__ __forceinline__ float tf32r(float x) {
    float y;
    asm("cvt.rna.tf32.f32 %0, %1;" : "=f"(y) : "f"(x));
    return y;
}

__device__ __forceinline__ void mma_tf32(
    float& c0, float& c1, float& c2, float& c3,
    uint32_t a0, uint32_t a1, uint32_t a2, uint32_t a3,
    uint32_t b0, uint32_t b1)
{
    asm volatile(
        "mma.sync.aligned.m16n8k8.row.col.f32.tf32.tf32.f32 "
        "{%0,%1,%2,%3}, {%4,%5,%6,%7}, {%8,%9}, {%0,%1,%2,%3};"
        : "+f"(c0), "+f"(c1), "+f"(c2), "+f"(c3)
        : "r"(a0), "r"(a1), "r"(a2), "r"(a3), "r"(b0), "r"(b1));
}

// --------------------------------------------------------- rel|mask pack ---
__global__ __launch_bounds__(256) void pack_rm_kernel(
    const int* __restrict__ rel, const int* __restrict__ relmask,
    int* __restrict__ rm)
{
    int i = blockIdx.x * 256 + threadIdx.x;
    rm[i] = rel[i] | (relmask[i] << 31);
}

// ------------------------------------------------------- tf32 MMA GEMM -----
// Register double-buffered staging (R13, known-good).
#define BM 64
#define BN 64
#define BKG 32
#define APAD 8
#define BPAD 8

__device__ __forceinline__ void gemm_tf32_body(
    const float* __restrict__ A, const float* __restrict__ B,
    const float* __restrict__ bias, float* __restrict__ C,
    int N, int K, int doRelu, int bm, int bn,
    float oscale, int roundOut)
{
    __shared__ float As[BKG][BM + APAD];   // [k][m]
    __shared__ float Bs[BKG][BN + BPAD];   // [k][n]

    const int tid  = threadIdx.x;
    const int warp = tid >> 5;
    const int lane = tid & 31;
    const int wm = (warp & 3) * 16;
    const int wn = (warp >> 2) * 32;
    const int g  = lane >> 2;
    const int tg = lane & 3;

    float acc[4][4];
#pragma unroll
    for (int i = 0; i < 4; i++)
#pragma unroll
        for (int j = 0; j < 4; j++) acc[i][j] = 0.f;

    const int ar0 = tid >> 3;
    const int ac0 = (tid & 7) * 4;
    const int br0 = tid >> 4;
    const int bc0 = (tid & 15) * 4;

    float4 av[2], bv[2];
#pragma unroll
    for (int it = 0; it < 2; it++) {
        av[it] = *(const float4*)(A + (size_t)(bm + ar0 + it * 32) * K + ac0);
        bv[it] = *(const float4*)(B + (size_t)(br0 + it * 16) * N + bn + bc0);
    }

    for (int k0 = 0; k0 < K; k0 += BKG) {
        __syncthreads();   // previous compute done reading smem
#pragma unroll
        for (int it = 0; it < 2; it++) {
            int arow = ar0 + it * 32;
            As[ac0 + 0][arow] = tf32r(av[it].x);
            As[ac0 + 1][arow] = tf32r(av[it].y);
            As[ac0 + 2][arow] = tf32r(av[it].z);
            As[ac0 + 3][arow] = tf32r(av[it].w);
            float4 bc;
            bc.x = tf32r(bv[it].x); bc.y = tf32r(bv[it].y);
            bc.z = tf32r(bv[it].z); bc.w = tf32r(bv[it].w);
            *(float4*)&Bs[br0 + it * 16][bc0] = bc;
        }
        __syncthreads();

        if (k0 + BKG < K) {
#pragma unroll
            for (int it = 0; it < 2; it++) {
                av[it] = *(const float4*)(A + (size_t)(bm + ar0 + it * 32) * K + k0 + BKG + ac0);
                bv[it] = *(const float4*)(B + (size_t)(k0 + BKG + br0 + it * 16) * N + bn + bc0);
            }
        }

#pragma unroll
        for (int ks = 0; ks < BKG; ks += 8) {
            uint32_t a0 = __float_as_uint(As[ks + tg    ][wm + g    ]);
            uint32_t a1 = __float_as_uint(As[ks + tg    ][wm + g + 8]);
            uint32_t a2 = __float_as_uint(As[ks + tg + 4][wm + g    ]);
            uint32_t a3 = __float_as_uint(As[ks + tg + 4][wm + g + 8]);
#pragma unroll
            for (int nt = 0; nt < 4; nt++) {
                uint32_t b0 = __float_as_uint(Bs[ks + tg    ][wn + nt * 8 + g]);
                uint32_t b1 = __float_as_uint(Bs[ks + tg + 4][wn + nt * 8 + g]);
                mma_tf32(acc[nt][0], acc[nt][1], acc[nt][2], acc[nt][3],
                         a0, a1, a2, a3, b0, b1);
            }
        }
    }

    const int row0 = bm + wm + g;
    const int colb = bn + wn + 2 * tg;
#pragma unroll
    for (int nt = 0; nt < 4; nt++) {
        int col = colb + nt * 8;
        float b0v = 0.f, b1v = 0.f;
        if (bias) { b0v = bias[col]; b1v = bias[col + 1]; }
        float2 o0, o1;
        o0.x = acc[nt][0] * oscale + b0v; o0.y = acc[nt][1] * oscale + b1v;
        o1.x = acc[nt][2] * oscale + b0v; o1.y = acc[nt][3] * oscale + b1v;
        if (doRelu) {
            o0.x = fmaxf(o0.x, 0.f); o0.y = fmaxf(o0.y, 0.f);
            o1.x = fmaxf(o1.x, 0.f); o1.y = fmaxf(o1.y, 0.f);
        }
        if (roundOut) {
            o0.x = tf32r(o0.x); o0.y = tf32r(o0.y);
            o1.x = tf32r(o1.x); o1.y = tf32r(o1.y);
        }
        *(float2*)(C + (size_t)row0 * N + col)       = o0;
        *(float2*)(C + (size_t)(row0 + 8) * N + col) = o1;
    }
}

__global__ __launch_bounds__(256) void gemm_kernel(
    const float* __restrict__ A, const float* __restrict__ B,
    const float* __restrict__ bias, float* __restrict__ C,
    int N, int K, int doRelu)
{
    gemm_tf32_body(A, B, bias, C, N, K, doRelu,
                   blockIdx.y * BM, blockIdx.x * BN, 1.f, 0);
}

__global__ __launch_bounds__(256) void gemm_qkv_kernel(
    const float* __restrict__ A,
    const float* __restrict__ Bq, const float* __restrict__ Bk,
    const float* __restrict__ Bv,
    float* __restrict__ Cq, float* __restrict__ Ck, float* __restrict__ Cv)
{
    const float* B = (blockIdx.z == 0) ? Bq : (blockIdx.z == 1) ? Bk : Bv;
    float*       C = (blockIdx.z == 0) ? Cq : (blockIdx.z == 1) ? Ck : Cv;
    float oscale = (blockIdx.z == 0) ? QSCALE : 1.f;
    gemm_tf32_body(A, B, nullptr, C, HH, HH, 0,
                   blockIdx.y * BM, blockIdx.x * BN, oscale, 1);
}

// ----------------------------------------------------- MMA Attention -------
// (R12/R13 body — fused softmax with shared atomics; known-good 385us config)
// Block = (i-tile of 16 rows, half the heads, batch). 128 thr, warp = head.
#define TI 16
#define TJ 32
#define HPB 4        // heads per block
#define EPR 36
#define EPH 580
#define KSR2 132     // 128 cols + 4 pad
#define VSR2 136     // 128 cols + 8 pad
#define RIR 34       // packed rel|mask row stride

// smem float offsets
#define SM_QREL 0                        // 64*101 = 6464
#define SM_EP   6464                     // 4*580  = 2320
#define SM_KS   8784                     // 32*132 = 4224
#define SM_VS   13008                    // 32*136 = 4352
#define SM_RI   17360                    // 16*34  = 544 (packed rel|mask<<31)
#define SM_CS   17904                    // 64
#define SM_W    17968                    // 64*101 = 6464
#define ATTN_SMEM_FLOATS 24432
#define ATTN_SMEM_BYTES  (ATTN_SMEM_FLOATS*4)   // 97728 B

__global__ __launch_bounds__(128, 2) void attn_kernel(
    const float* __restrict__ Q, const float* __restrict__ Kk,
    const float* __restrict__ V, const float* __restrict__ Ek,
    const float* __restrict__ Ev, const int* __restrict__ rm,
    float* __restrict__ O)
{
    extern __shared__ float sm[];
    float* QREL = sm + SM_QREL;              // [64][101]
    float* EP   = sm + SM_EP;                // [4][580]
    float* Ks   = sm + SM_KS;                // [32][132]
    float* Vs   = sm + SM_VS;                // [32][136]
    int*   ri   = (int*)(sm + SM_RI);        // [16][34] packed
    float* Cs   = sm + SM_CS;                // [64]
    float* Wh   = sm + SM_W;                 // [64][101]

    const int tid  = threadIdx.x;
    const int b    = blockIdx.y >> 1;
    const int hg   = blockIdx.y & 1;         // head half
    const int hbase= hg * HPB;
    const int i0   = blockIdx.x * TI;
    const int row0 = b * LL + i0;
    const int w    = tid >> 5;               // local head 0..3
    const int lane = tid & 31;
    const int g    = lane >> 2;
    const int tg   = lane & 3;

    // ---- QREL precompute: 64 rows x 100 rels; two threads per row ----
    {
        const int pr = tid & 63;             // row: lh = pr>>4, il = pr&15
        const int h  = hbase + (pr >> 4);
        const int il = pr & 15;
        float ql[32];
        const float4* qp = (const float4*)(Q + (size_t)(row0 + il) * HH + h * DHEAD);
#pragma unroll
        for (int d4 = 0; d4 < 8; d4++) {
            float4 v4 = qp[d4];
            ql[d4*4+0] = v4.x; ql[d4*4+1] = v4.y;
            ql[d4*4+2] = v4.z; ql[d4*4+3] = v4.w;
        }
        float* qrow = QREL + pr * 101;
        const int r0 = (tid >> 6) * 50;
#pragma unroll 2
        for (int r = r0; r < r0 + 50; r++) {
            const float4* e4 = (const float4*)(Ek + r * 32);
            float d0 = 0.f, d1 = 0.f, d2 = 0.f, d3 = 0.f;
#pragma unroll
            for (int d4 = 0; d4 < 8; d4++) {
                float4 ev = e4[d4];
                d0 += ql[d4*4+0] * ev.x; d1 += ql[d4*4+1] * ev.y;
                d2 += ql[d4*4+2] * ev.z; d3 += ql[d4*4+3] * ev.w;
            }
            qrow[r] = (d0 + d1) + (d2 + d3);
        }
    }

    // ---- stage Q (this block's 4 heads) into EP ----
#pragma unroll
    for (int q = 0; q < 4; q++) {
        int f  = tid + q * 128;              // 0..511 float4 slots (16 rows x 32)
        int i  = f >> 5;
        int hc = f & 31;
        int hh = hc >> 3, d4 = hc & 7;
        float4 v4 = ((const float4*)Q)[(size_t)(row0 + i) * 64 + hg * 32 + hc];
        *(float4*)&EP[hh * EPH + i * EPR + d4 * 4] = v4;
    }

    // ---- zero relation histogram ----
    for (int f = tid; f < 64 * 101; f += 128) Wh[f] = 0.f;
    __syncthreads();

    // ---- preload Q fragments ----
    uint32_t qa[4][4];
    {
        const float* eph = EP + w * EPH;
#pragma unroll
        for (int ks = 0; ks < 4; ks++) {
            qa[ks][0] = __float_as_uint(eph[ g      * EPR + tg     + 8*ks]);
            qa[ks][1] = __float_as_uint(eph[(g + 8) * EPR + tg     + 8*ks]);
            qa[ks][2] = __float_as_uint(eph[ g      * EPR + tg + 4 + 8*ks]);
            qa[ks][3] = __float_as_uint(eph[(g + 8) * EPR + tg + 4 + 8*ks]);
        }
    }

    float s0 = 0.f, s1 = 0.f;    // partial row sums (rows g, g+8) over own cols
    float oa[4][4];
#pragma unroll
    for (int ns = 0; ns < 4; ns++)
#pragma unroll
        for (int c = 0; c < 4; c++) oa[ns][c] = 0.f;

    const float* qrow_g  = QREL + (w * 16 + g    ) * 101;
    const float* qrow_g8 = QREL + (w * 16 + g + 8) * 101;
    float* wh_g  = Wh + (w * 16 + g    ) * 101;
    float* wh_g8 = Wh + (w * 16 + g + 8) * 101;
    const float4* kg4 = (const float4*)Kk;
    const float4* vg4 = (const float4*)V;

    const int NT = LL / TJ;
    for (int t = 0; t < NT; t++) {
        const int j0 = t * TJ;
        // ---- stage K/V (block's 128 cols) + packed rel|mask ----
#pragma unroll
        for (int q = 0; q < 8; q++) {
            int f  = tid + q * 128;          // 0..1023 float4 slots
            int jj = f >> 5;
            int c4 = f & 31;
            int gi = (b * LL + j0 + jj) * 64 + hg * 32 + c4;
            *(float4*)&Ks[jj * KSR2 + c4 * 4] = kg4[gi];
            *(float4*)&Vs[jj * VSR2 + c4 * 4] = vg4[gi];
        }
#pragma unroll
        for (int q = 0; q < 4; q++) {
            int f  = tid + q * 128;          // 0..511
            int ii = f >> 5, jj = f & 31;
            ri[ii * RIR + jj] = rm[(size_t)(row0 + ii) * LL + j0 + jj];
        }
        __syncthreads();

        // ---- score MMA + fused softmax (all in fragment owners) ----
        {
            float* eph = EP + w * EPH;
            const float* ksh = Ks + w * 32;
            const int* rr0 = ri + g * RIR;
            const int* rr1 = ri + (g + 8) * RIR;
#pragma unroll
            for (int ns = 0; ns < 4; ns++) {
                float e0 = 0.f, e1 = 0.f, e2 = 0.f, e3 = 0.f;
                const float* kb = ksh + (ns * 8 + g) * KSR2;
#pragma unroll
                for (int ks = 0; ks < 4; ks++) {
                    uint32_t b0 = __float_as_uint(kb[tg     + 8*ks]);
                    uint32_t b1 = __float_as_uint(kb[tg + 4 + 8*ks]);
                    mma_tf32(e0, e1, e2, e3,
                             qa[ks][0], qa[ks][1], qa[ks][2], qa[ks][3], b0, b1);
                }
                const int c0 = ns * 8 + 2 * tg;
                int va0 = rr0[c0], va1 = rr0[c0 + 1];
                int vb0 = rr1[c0], vb1 = rr1[c0 + 1];
                int ra0 = va0 & 0x7fffffff, ra1 = va1 & 0x7fffffff;
                int rb0 = vb0 & 0x7fffffff, rb1 = vb1 & 0x7fffffff;
                float p00 = (va0 < 0) ? 0.f : ex2f(e0 + qrow_g [ra0]);
                float p01 = (va1 < 0) ? 0.f : ex2f(e1 + qrow_g [ra1]);
                float p10 = (vb0 < 0) ? 0.f : ex2f(e2 + qrow_g8[rb0]);
                float p11 = (vb1 < 0) ? 0.f : ex2f(e3 + qrow_g8[rb1]);
                s0 += p00 + p01;
                s1 += p10 + p11;
                atomicAdd(wh_g  + ra0, p00);
                atomicAdd(wh_g  + ra1, p01);
                atomicAdd(wh_g8 + rb0, p10);
                atomicAdd(wh_g8 + rb1, p11);
                *(float2*)&eph[ g      * EPR + c0] = make_float2(tf32r(p00), tf32r(p01));
                *(float2*)&eph[(g + 8) * EPR + c0] = make_float2(tf32r(p10), tf32r(p11));
            }
        }
        __syncwarp();

        // ---- AV MMA: o += P(16x32) . V(32x32) ----
        {
            const float* eph = EP + w * EPH;
#pragma unroll
            for (int ks = 0; ks < 4; ks++) {
                uint32_t pa0 = __float_as_uint(eph[ g      * EPR + tg     + 8*ks]);
                uint32_t pa1 = __float_as_uint(eph[(g + 8) * EPR + tg     + 8*ks]);
                uint32_t pa2 = __float_as_uint(eph[ g      * EPR + tg + 4 + 8*ks]);
                uint32_t pa3 = __float_as_uint(eph[(g + 8) * EPR + tg + 4 + 8*ks]);
                const float* vb0 = Vs + (ks * 8 + tg    ) * VSR2 + w * 32;
                const float* vb1 = Vs + (ks * 8 + tg + 4) * VSR2 + w * 32;
#pragma unroll
                for (int ns = 0; ns < 4; ns++) {
                    uint32_t b0 = __float_as_uint(vb0[ns * 8 + g]);
                    uint32_t b1 = __float_as_uint(vb1[ns * 8 + g]);
                    mma_tf32(oa[ns][0], oa[ns][1], oa[ns][2], oa[ns][3],
                             pa0, pa1, pa2, pa3, b0, b1);
                }
            }
        }
        __syncthreads();   // Ks/Vs/ri fully consumed before restaging
    }

    // ---- row-sum reduction across the tg quartet ----
    s0 += __shfl_xor_sync(0xffffffffu, s0, 1);
    s0 += __shfl_xor_sync(0xffffffffu, s0, 2);
    s1 += __shfl_xor_sync(0xffffffffu, s1, 1);
    s1 += __shfl_xor_sync(0xffffffffu, s1, 2);

    // ---- epilogue: o frags + row sums -> smem ----
    {
        float* eph = EP + w * EPH;
#pragma unroll
        for (int ns = 0; ns < 4; ns++) {
            *(float2*)&eph[ g      * EPR + ns * 8 + 2*tg] = make_float2(oa[ns][0], oa[ns][1]);
            *(float2*)&eph[(g + 8) * EPR + ns * 8 + 2*tg] = make_float2(oa[ns][2], oa[ns][3]);
        }
        if (tg == 0) {
            Cs[w * 16 + g]     = s0;
            Cs[w * 16 + g + 8] = s1;
        }
    }
    // stage Ev into Ks region (3200 floats, fits in 4224)
    for (int f = tid; f < RELN * 32; f += 128) Ks[f] = Ev[f];
    __syncthreads();

    if (tid < 64) {
        const int lh = tid >> 4, il = tid & 15;
        const int h  = hbase + lh;
        const float* orow = EP + lh * EPH + il * EPR;
        const float* wrd  = Wh + tid * 101;
        float of[32];
#pragma unroll
        for (int d = 0; d < 32; d++) of[d] = orow[d];
#pragma unroll 2
        for (int r = 0; r < RELN; r++) {
            float wv = wrd[r];
            const float4* ev4 = (const float4*)(Ks + r * 32);
#pragma unroll
            for (int d4 = 0; d4 < 8; d4++) {
                float4 ev = ev4[d4];
                of[d4*4+0] += wv * ev.x; of[d4*4+1] += wv * ev.y;
                of[d4*4+2] += wv * ev.z; of[d4*4+3] += wv * ev.w;
            }
        }
        float inv = 1.f / Cs[tid];
        float* op = O + (size_t)(row0 + il) * HH + h * 32;
#pragma unroll
        for (int d4 = 0; d4 < 8; d4++) {
            float4 v4;
            v4.x = of[d4*4+0] * inv; v4.y = of[d4*4+1] * inv;
            v4.z = of[d4*4+2] * inv; v4.w = of[d4*4+3] * inv;
            *(float4*)(op + d4 * 4) = v4;
        }
    }
}

// ------------------------------------------------- Residual + LayerNorm ----
// warp-per-row, float4, shfl-only (R15, known-good). 8 rows/block.
__global__ __launch_bounds__(256) void ln_kernel(
    const float* __restrict__ X, const float* __restrict__ Y,
    const float* __restrict__ g, const float* __restrict__ bta,
    float* __restrict__ Out)
{
    const int warp = threadIdx.x >> 5;
    const int lane = threadIdx.x & 31;
    const int r = blockIdx.x * 8 + warp;

    const float4* x4 = (const float4*)(X + (size_t)r * HH) + lane * 2;
    const float4* y4 = (const float4*)(Y + (size_t)r * HH) + lane * 2;
    float4 a0 = x4[0], a1 = x4[1];
    float4 b0 = y4[0], b1 = y4[1];
    float v[8];
    v[0] = a0.x + b0.x; v[1] = a0.y + b0.y; v[2] = a0.z + b0.z; v[3] = a0.w + b0.w;
    v[4] = a1.x + b1.x; v[5] = a1.y + b1.y; v[6] = a1.z + b1.z; v[7] = a1.w + b1.w;

    float s1 = 0.f, s2 = 0.f;
#pragma unroll
    for (int d = 0; d < 8; d++) { s1 += v[d]; s2 += v[d] * v[d]; }
#pragma unroll
    for (int o = 16; o; o >>= 1) {
        s1 += __shfl_xor_sync(0xffffffffu, s1, o);
        s2 += __shfl_xor_sync(0xffffffffu, s2, o);
    }
    float mean = s1 * (1.f / HH);
    float var  = s2 * (1.f / HH) - mean * mean;
    float rstd = rsqrtf(var + EPSLN);

    const float4* g4 = (const float4*)g + lane * 2;
    const float4* t4 = (const float4*)bta + lane * 2;
    float4 gg0 = g4[0], gg1 = g4[1];
    float4 tt0 = t4[0], tt1 = t4[1];
    float4 o0, o1;
    o0.x = (v[0] - mean) * rstd * gg0.x + tt0.x;
    o0.y = (v[1] - mean) * rstd * gg0.y + tt0.y;
    o0.z = (v[2] - mean) * rstd * gg0.z + tt0.z;
    o0.w = (v[3] - mean) * rstd * gg0.w + tt0.w;
    o1.x = (v[4] - mean) * rstd * gg1.x + tt1.x;
    o1.y = (v[5] - mean) * rstd * gg1.y + tt1.y;
    o1.z = (v[6] - mean) * rstd * gg1.z + tt1.z;
    o1.w = (v[7] - mean) * rstd * gg1.w + tt1.w;
    float4* out4 = (float4*)(Out + (size_t)r * HH) + lane * 2;
    out4[0] = o0;
    out4[1] = o1;
}

// ------------------------------------------------------------- launcher ----
extern "C" void kernel_launch(void* const* d_in, const int* in_sizes, int n_in,
                              void* d_out, int out_size)
{
    const float* inputs = (const float*)d_in[0];
    const float* Wq  = (const float*)d_in[1];
    const float* Wk  = (const float*)d_in[2];
    const float* Wv  = (const float*)d_in[3];
    const float* Wo  = (const float*)d_in[4];
    const float* bo  = (const float*)d_in[5];
    const float* W1  = (const float*)d_in[6];
    const float* b1  = (const float*)d_in[7];
    const float* W2  = (const float*)d_in[8];
    const float* b2  = (const float*)d_in[9];
    const float* ln1g = (const float*)d_in[10];
    const float* ln1b = (const float*)d_in[11];
    const float* ln2g = (const float*)d_in[12];
    const float* ln2b = (const float*)d_in[13];
    const float* Ek  = (const float*)d_in[14];
    const float* Ev  = (const float*)d_in[15];
    const int*   rel = (const int*)d_in[16];
    const int*   rmask = (const int*)d_in[17];
    float* out = (float*)d_out;

    float *qb, *kb, *vb, *ab, *yb, *xb, *fb;
    int *rmb;
    cudaGetSymbolAddress((void**)&qb, g_qb);
    cudaGetSymbolAddress((void**)&kb, g_kb);
    cudaGetSymbolAddress((void**)&vb, g_vb);
    cudaGetSymbolAddress((void**)&ab, g_ab);
    cudaGetSymbolAddress((void**)&yb, g_yb);
    cudaGetSymbolAddress((void**)&xb, g_xb);
    cudaGetSymbolAddress((void**)&fb, g_fb);
    cudaGetSymbolAddress((void**)&rmb, g_rm);

    cudaFuncSetAttribute(attn_kernel,
                         cudaFuncAttributeMaxDynamicSharedMemorySize,
                         ATTN_SMEM_BYTES);

    pack_rm_kernel<<<(BB*LL*LL)/256, 256>>>(rel, rmask, rmb);

    for (int l = 0; l < NLAYER; l++) {
        const float* x = (l == 0) ? inputs : xb;
        const size_t wHH = (size_t)l * HH * HH;
        const size_t wHF = (size_t)l * HH * FFD;

        gemm_qkv_kernel<<<dim3(HH/BN, ROWS/BM, 3), 256>>>(
            x, Wq + wHH, Wk + wHH, Wv + wHH, qb, kb, vb);

        attn_kernel<<<dim3(LL/TI, BB*2), 128, ATTN_SMEM_BYTES>>>(qb, kb, vb, Ek, Ev, rmb, ab);

        gemm_kernel<<<dim3(HH/BN, ROWS/BM), 256>>>(ab, Wo + wHH, bo + l*HH, yb, HH, HH, 0);
        ln_kernel<<<ROWS/8, 256>>>(x, yb, ln1g + l*HH, ln1b + l*HH, xb);

        gemm_kernel<<<dim3(FFD/BN, ROWS/BM), 256>>>(xb, W1 + wHF, b1 + l*FFD, fb, FFD, HH, 1);
        gemm_kernel<<<dim3(HH/BN, ROWS/BM), 256>>>(fb, W2 + wHF, b2 + l*HH, yb, HH, FFD, 0);
        ln_kernel<<<ROWS/8, 256>>>(xb, yb, ln2g + l*HH, ln2b + l*HH, (l == NLAYER-1) ? out : xb);
    }
}

// round 17
// speedup vs baseline: 1.5654x; 1.5654x over previous
#include <cuda_runtime.h>
#include <math.h>
#include <stdint.h>

// Problem constants
#define BB 2
#define LL 1024
#define HH 256
#define NHEAD 8
#define DHEAD 32
#define FFD 1024
#define NLAYER 2
#define RELN 100
#define EPSLN 1e-5f
// 1/sqrt(32) * log2(e)  (exp done in base 2)
#define QSCALE (0.17677669529663687f * 1.4426950408889634f)

#define ROWS (BB*LL)          // 2048

// ---------------- scratch (static device memory; no allocations allowed) ----
__device__ float g_qb[ROWS*HH];
__device__ float g_kb[ROWS*HH];
__device__ float g_vb[ROWS*HH];
__device__ float g_ab[ROWS*HH];
__device__ float g_yb[ROWS*HH];
__device__ float g_xb[ROWS*HH];
__device__ float g_fb[ROWS*FFD];

__device__ __forceinline__ float ex2f(float x) {
    float y;
    asm("ex2.approx.ftz.f32 %0, %1;" : "=f"(y) : "f"(x));
    return y;
}

__device__ __forceinline__ float tf32r(float x) {
    float y;
    asm("cvt.rna.tf32.f32 %0, %1;" : "=f"(y) : "f"(x));
    return y;
}

__device__ __forceinline__ void mma_tf32(
    float& c0, float& c1, float& c2, float& c3,
    uint32_t a0, uint32_t a1, uint32_t a2, uint32_t a3,
    uint32_t b0, uint32_t b1)
{
    asm volatile(
        "mma.sync.aligned.m16n8k8.row.col.f32.tf32.tf32.f32 "
        "{%0,%1,%2,%3}, {%4,%5,%6,%7}, {%8,%9}, {%0,%1,%2,%3};"
        : "+f"(c0), "+f"(c1), "+f"(c2), "+f"(c3)
        : "r"(a0), "r"(a1), "r"(a2), "r"(a3), "r"(b0), "r"(b1));
}

// ------------------------------------------------------- tf32 MMA GEMM -----
// Register double-buffered staging (R13, known-good).
#define BM 64
#define BN 64
#define BKG 32
#define APAD 8
#define BPAD 8

__device__ __forceinline__ void gemm_tf32_body(
    const float* __restrict__ A, const float* __restrict__ B,
    const float* __restrict__ bias, float* __restrict__ C,
    int N, int K, int doRelu, int bm, int bn,
    float oscale, int roundOut)
{
    __shared__ float As[BKG][BM + APAD];   // [k][m]
    __shared__ float Bs[BKG][BN + BPAD];   // [k][n]

    const int tid  = threadIdx.x;
    const int warp = tid >> 5;
    const int lane = tid & 31;
    const int wm = (warp & 3) * 16;
    const int wn = (warp >> 2) * 32;
    const int g  = lane >> 2;
    const int tg = lane & 3;

    float acc[4][4];
#pragma unroll
    for (int i = 0; i < 4; i++)
#pragma unroll
        for (int j = 0; j < 4; j++) acc[i][j] = 0.f;

    const int ar0 = tid >> 3;
    const int ac0 = (tid & 7) * 4;
    const int br0 = tid >> 4;
    const int bc0 = (tid & 15) * 4;

    float4 av[2], bv[2];
#pragma unroll
    for (int it = 0; it < 2; it++) {
        av[it] = *(const float4*)(A + (size_t)(bm + ar0 + it * 32) * K + ac0);
        bv[it] = *(const float4*)(B + (size_t)(br0 + it * 16) * N + bn + bc0);
    }

    for (int k0 = 0; k0 < K; k0 += BKG) {
        __syncthreads();   // previous compute done reading smem
#pragma unroll
        for (int it = 0; it < 2; it++) {
            int arow = ar0 + it * 32;
            As[ac0 + 0][arow] = tf32r(av[it].x);
            As[ac0 + 1][arow] = tf32r(av[it].y);
            As[ac0 + 2][arow] = tf32r(av[it].z);
            As[ac0 + 3][arow] = tf32r(av[it].w);
            float4 bc;
            bc.x = tf32r(bv[it].x); bc.y = tf32r(bv[it].y);
            bc.z = tf32r(bv[it].z); bc.w = tf32r(bv[it].w);
            *(float4*)&Bs[br0 + it * 16][bc0] = bc;
        }
        __syncthreads();

        if (k0 + BKG < K) {
#pragma unroll
            for (int it = 0; it < 2; it++) {
                av[it] = *(const float4*)(A + (size_t)(bm + ar0 + it * 32) * K + k0 + BKG + ac0);
                bv[it] = *(const float4*)(B + (size_t)(k0 + BKG + br0 + it * 16) * N + bn + bc0);
            }
        }

#pragma unroll
        for (int ks = 0; ks < BKG; ks += 8) {
            uint32_t a0 = __float_as_uint(As[ks + tg    ][wm + g    ]);
            uint32_t a1 = __float_as_uint(As[ks + tg    ][wm + g + 8]);
            uint32_t a2 = __float_as_uint(As[ks + tg + 4][wm + g    ]);
            uint32_t a3 = __float_as_uint(As[ks + tg + 4][wm + g + 8]);
#pragma unroll
            for (int nt = 0; nt < 4; nt++) {
                uint32_t b0 = __float_as_uint(Bs[ks + tg    ][wn + nt * 8 + g]);
                uint32_t b1 = __float_as_uint(Bs[ks + tg + 4][wn + nt * 8 + g]);
                mma_tf32(acc[nt][0], acc[nt][1], acc[nt][2], acc[nt][3],
                         a0, a1, a2, a3, b0, b1);
            }
        }
    }

    const int row0 = bm + wm + g;
    const int colb = bn + wn + 2 * tg;
#pragma unroll
    for (int nt = 0; nt < 4; nt++) {
        int col = colb + nt * 8;
        float b0v = 0.f, b1v = 0.f;
        if (bias) { b0v = bias[col]; b1v = bias[col + 1]; }
        float2 o0, o1;
        o0.x = acc[nt][0] * oscale + b0v; o0.y = acc[nt][1] * oscale + b1v;
        o1.x = acc[nt][2] * oscale + b0v; o1.y = acc[nt][3] * oscale + b1v;
        if (doRelu) {
            o0.x = fmaxf(o0.x, 0.f); o0.y = fmaxf(o0.y, 0.f);
            o1.x = fmaxf(o1.x, 0.f); o1.y = fmaxf(o1.y, 0.f);
        }
        if (roundOut) {
            o0.x = tf32r(o0.x); o0.y = tf32r(o0.y);
            o1.x = tf32r(o1.x); o1.y = tf32r(o1.y);
        }
        *(float2*)(C + (size_t)row0 * N + col)       = o0;
        *(float2*)(C + (size_t)(row0 + 8) * N + col) = o1;
    }
}

__global__ __launch_bounds__(256) void gemm_kernel(
    const float* __restrict__ A, const float* __restrict__ B,
    const float* __restrict__ bias, float* __restrict__ C,
    int N, int K, int doRelu)
{
    gemm_tf32_body(A, B, bias, C, N, K, doRelu,
                   blockIdx.y * BM, blockIdx.x * BN, 1.f, 0);
}

__global__ __launch_bounds__(256) void gemm_qkv_kernel(
    const float* __restrict__ A,
    const float* __restrict__ Bq, const float* __restrict__ Bk,
    const float* __restrict__ Bv,
    float* __restrict__ Cq, float* __restrict__ Ck, float* __restrict__ Cv)
{
    const float* B = (blockIdx.z == 0) ? Bq : (blockIdx.z == 1) ? Bk : Bv;
    float*       C = (blockIdx.z == 0) ? Cq : (blockIdx.z == 1) ? Ck : Cv;
    float oscale = (blockIdx.z == 0) ? QSCALE : 1.f;
    gemm_tf32_body(A, B, nullptr, C, HH, HH, 0,
                   blockIdx.y * BM, blockIdx.x * BN, oscale, 1);
}

// ----------------------------------------------------- MMA Attention -------
// (R13 body exactly — fused softmax with shared atomics; measured 385us)
// Block = (i-tile of 16 rows, half the heads, batch). 128 thr, warp = head.
#define TI 16
#define TJ 32
#define HPB 4        // heads per block
#define EPR 36
#define EPH 580
#define KSR2 132     // 128 cols + 4 pad
#define VSR2 136     // 128 cols + 8 pad
#define RIR 34       // packed rel|mask row stride

// smem float offsets
#define SM_QREL 0                        // 64*101 = 6464
#define SM_EP   6464                     // 4*580  = 2320
#define SM_KS   8784                     // 32*132 = 4224
#define SM_VS   13008                    // 32*136 = 4352
#define SM_RI   17360                    // 16*34  = 544 (packed rel|mask<<31)
#define SM_CS   17904                    // 64
#define SM_W    17968                    // 64*101 = 6464
#define ATTN_SMEM_FLOATS 24432
#define ATTN_SMEM_BYTES  (ATTN_SMEM_FLOATS*4)   // 97728 B

__global__ __launch_bounds__(128, 2) void attn_kernel(
    const float* __restrict__ Q, const float* __restrict__ Kk,
    const float* __restrict__ V, const float* __restrict__ Ek,
    const float* __restrict__ Ev, const int* __restrict__ rel,
    const int* __restrict__ relmask, float* __restrict__ O)
{
    extern __shared__ float sm[];
    float* QREL = sm + SM_QREL;              // [64][101]
    float* EP   = sm + SM_EP;                // [4][580]
    float* Ks   = sm + SM_KS;                // [32][132]
    float* Vs   = sm + SM_VS;                // [32][136]
    int*   ri   = (int*)(sm + SM_RI);        // [16][34] packed
    float* Cs   = sm + SM_CS;                // [64]
    float* Wh   = sm + SM_W;                 // [64][101]

    const int tid  = threadIdx.x;
    const int b    = blockIdx.y >> 1;
    const int hg   = blockIdx.y & 1;         // head half
    const int hbase= hg * HPB;
    const int i0   = blockIdx.x * TI;
    const int row0 = b * LL + i0;
    const int w    = tid >> 5;               // local head 0..3
    const int lane = tid & 31;
    const int g    = lane >> 2;
    const int tg   = lane & 3;

    // ---- QREL precompute: 64 rows x 100 rels; two threads per row ----
    {
        const int pr = tid & 63;             // row: lh = pr>>4, il = pr&15
        const int h  = hbase + (pr >> 4);
        const int il = pr & 15;
        float ql[32];
        const float4* qp = (const float4*)(Q + (size_t)(row0 + il) * HH + h * DHEAD);
#pragma unroll
        for (int d4 = 0; d4 < 8; d4++) {
            float4 v4 = qp[d4];
            ql[d4*4+0] = v4.x; ql[d4*4+1] = v4.y;
            ql[d4*4+2] = v4.z; ql[d4*4+3] = v4.w;
        }
        float* qrow = QREL + pr * 101;
        const int r0 = (tid >> 6) * 50;
#pragma unroll 2
        for (int r = r0; r < r0 + 50; r++) {
            const float4* e4 = (const float4*)(Ek + r * 32);
            float d0 = 0.f, d1 = 0.f, d2 = 0.f, d3 = 0.f;
#pragma unroll
            for (int d4 = 0; d4 < 8; d4++) {
                float4 ev = e4[d4];
                d0 += ql[d4*4+0] * ev.x; d1 += ql[d4*4+1] * ev.y;
                d2 += ql[d4*4+2] * ev.z; d3 += ql[d4*4+3] * ev.w;
            }
            qrow[r] = (d0 + d1) + (d2 + d3);
        }
    }

    // ---- stage Q (this block's 4 heads) into EP ----
#pragma unroll
    for (int q = 0; q < 4; q++) {
        int f  = tid + q * 128;              // 0..511 float4 slots (16 rows x 32)
        int i  = f >> 5;
        int hc = f & 31;
        int hh = hc >> 3, d4 = hc & 7;
        float4 v4 = ((const float4*)Q)[(size_t)(row0 + i) * 64 + hg * 32 + hc];
        *(float4*)&EP[hh * EPH + i * EPR + d4 * 4] = v4;
    }

    // ---- zero relation histogram ----
    for (int f = tid; f < 64 * 101; f += 128) Wh[f] = 0.f;
    __syncthreads();

    // ---- preload Q fragments ----
    uint32_t qa[4][4];
    {
        const float* eph = EP + w * EPH;
#pragma unroll
        for (int ks = 0; ks < 4; ks++) {
            qa[ks][0] = __float_as_uint(eph[ g      * EPR + tg     + 8*ks]);
            qa[ks][1] = __float_as_uint(eph[(g + 8) * EPR + tg     + 8*ks]);
            qa[ks][2] = __float_as_uint(eph[ g      * EPR + tg + 4 + 8*ks]);
            qa[ks][3] = __float_as_uint(eph[(g + 8) * EPR + tg + 4 + 8*ks]);
        }
    }

    float s0 = 0.f, s1 = 0.f;    // partial row sums (rows g, g+8) over own cols
    float oa[4][4];
#pragma unroll
    for (int ns = 0; ns < 4; ns++)
#pragma unroll
        for (int c = 0; c < 4; c++) oa[ns][c] = 0.f;

    const float* qrow_g  = QREL + (w * 16 + g    ) * 101;
    const float* qrow_g8 = QREL + (w * 16 + g + 8) * 101;
    float* wh_g  = Wh + (w * 16 + g    ) * 101;
    float* wh_g8 = Wh + (w * 16 + g + 8) * 101;
    const float4* kg4 = (const float4*)Kk;
    const float4* vg4 = (const float4*)V;

    const int NT = LL / TJ;
    for (int t = 0; t < NT; t++) {
        const int j0 = t * TJ;
        // ---- stage K/V (block's 128 cols) + packed rel|mask ----
#pragma unroll
        for (int q = 0; q < 8; q++) {
            int f  = tid + q * 128;          // 0..1023 float4 slots
            int jj = f >> 5;
            int c4 = f & 31;
            int gi = (b * LL + j0 + jj) * 64 + hg * 32 + c4;
            *(float4*)&Ks[jj * KSR2 + c4 * 4] = kg4[gi];
            *(float4*)&Vs[jj * VSR2 + c4 * 4] = vg4[gi];
        }
#pragma unroll
        for (int q = 0; q < 4; q++) {
            int f  = tid + q * 128;          // 0..511
            int ii = f >> 5, jj = f & 31;
            size_t gi = (size_t)(row0 + ii) * LL + j0 + jj;
            ri[ii * RIR + jj] = rel[gi] | (relmask[gi] << 31);
        }
        __syncthreads();

        // ---- score MMA + fused softmax (all in fragment owners) ----
        {
            float* eph = EP + w * EPH;
            const float* ksh = Ks + w * 32;
            const int* rr0 = ri + g * RIR;
            const int* rr1 = ri + (g + 8) * RIR;
#pragma unroll
            for (int ns = 0; ns < 4; ns++) {
                float e0 = 0.f, e1 = 0.f, e2 = 0.f, e3 = 0.f;
                const float* kb = ksh + (ns * 8 + g) * KSR2;
#pragma unroll
                for (int ks = 0; ks < 4; ks++) {
                    uint32_t b0 = __float_as_uint(kb[tg     + 8*ks]);
                    uint32_t b1 = __float_as_uint(kb[tg + 4 + 8*ks]);
                    mma_tf32(e0, e1, e2, e3,
                             qa[ks][0], qa[ks][1], qa[ks][2], qa[ks][3], b0, b1);
                }
                const int c0 = ns * 8 + 2 * tg;
                int va0 = rr0[c0], va1 = rr0[c0 + 1];
                int vb0 = rr1[c0], vb1 = rr1[c0 + 1];
                int ra0 = va0 & 0x7fffffff, ra1 = va1 & 0x7fffffff;
                int rb0 = vb0 & 0x7fffffff, rb1 = vb1 & 0x7fffffff;
                float p00 = (va0 < 0) ? 0.f : ex2f(e0 + qrow_g [ra0]);
                float p01 = (va1 < 0) ? 0.f : ex2f(e1 + qrow_g [ra1]);
                float p10 = (vb0 < 0) ? 0.f : ex2f(e2 + qrow_g8[rb0]);
                float p11 = (vb1 < 0) ? 0.f : ex2f(e3 + qrow_g8[rb1]);
                s0 += p00 + p01;
                s1 += p10 + p11;
                atomicAdd(wh_g  + ra0, p00);
                atomicAdd(wh_g  + ra1, p01);
                atomicAdd(wh_g8 + rb0, p10);
                atomicAdd(wh_g8 + rb1, p11);
                *(float2*)&eph[ g      * EPR + c0] = make_float2(tf32r(p00), tf32r(p01));
                *(float2*)&eph[(g + 8) * EPR + c0] = make_float2(tf32r(p10), tf32r(p11));
            }
        }
        __syncwarp();

        // ---- AV MMA: o += P(16x32) . V(32x32) ----
        {
            const float* eph = EP + w * EPH;
#pragma unroll
            for (int ks = 0; ks < 4; ks++) {
                uint32_t pa0 = __float_as_uint(eph[ g      * EPR + tg     + 8*ks]);
                uint32_t pa1 = __float_as_uint(eph[(g + 8) * EPR + tg     + 8*ks]);
                uint32_t pa2 = __float_as_uint(eph[ g      * EPR + tg + 4 + 8*ks]);
                uint32_t pa3 = __float_as_uint(eph[(g + 8) * EPR + tg + 4 + 8*ks]);
                const float* vb0 = Vs + (ks * 8 + tg    ) * VSR2 + w * 32;
                const float* vb1 = Vs + (ks * 8 + tg + 4) * VSR2 + w * 32;
#pragma unroll
                for (int ns = 0; ns < 4; ns++) {
                    uint32_t b0 = __float_as_uint(vb0[ns * 8 + g]);
                    uint32_t b1 = __float_as_uint(vb1[ns * 8 + g]);
                    mma_tf32(oa[ns][0], oa[ns][1], oa[ns][2], oa[ns][3],
                             pa0, pa1, pa2, pa3, b0, b1);
                }
            }
        }
        __syncthreads();   // Ks/Vs/ri fully consumed before restaging
    }

    // ---- row-sum reduction across the tg quartet ----
    s0 += __shfl_xor_sync(0xffffffffu, s0, 1);
    s0 += __shfl_xor_sync(0xffffffffu, s0, 2);
    s1 += __shfl_xor_sync(0xffffffffu, s1, 1);
    s1 += __shfl_xor_sync(0xffffffffu, s1, 2);

    // ---- epilogue: o frags + row sums -> smem ----
    {
        float* eph = EP + w * EPH;
#pragma unroll
        for (int ns = 0; ns < 4; ns++) {
            *(float2*)&eph[ g      * EPR + ns * 8 + 2*tg] = make_float2(oa[ns][0], oa[ns][1]);
            *(float2*)&eph[(g + 8) * EPR + ns * 8 + 2*tg] = make_float2(oa[ns][2], oa[ns][3]);
        }
        if (tg == 0) {
            Cs[w * 16 + g]     = s0;
            Cs[w * 16 + g + 8] = s1;
        }
    }
    // stage Ev into Ks region (3200 floats, fits in 4224)
    for (int f = tid; f < RELN * 32; f += 128) Ks[f] = Ev[f];
    __syncthreads();

    if (tid < 64) {
        const int lh = tid >> 4, il = tid & 15;
        const int h  = hbase + lh;
        const float* orow = EP + lh * EPH + il * EPR;
        const float* wrd  = Wh + tid * 101;
        float of[32];
#pragma unroll
        for (int d = 0; d < 32; d++) of[d] = orow[d];
#pragma unroll 2
        for (int r = 0; r < RELN; r++) {
            float wv = wrd[r];
            const float4* ev4 = (const float4*)(Ks + r * 32);
#pragma unroll
            for (int d4 = 0; d4 < 8; d4++) {
                float4 ev = ev4[d4];
                of[d4*4+0] += wv * ev.x; of[d4*4+1] += wv * ev.y;
                of[d4*4+2] += wv * ev.z; of[d4*4+3] += wv * ev.w;
            }
        }
        float inv = 1.f / Cs[tid];
        float* op = O + (size_t)(row0 + il) * HH + h * 32;
#pragma unroll
        for (int d4 = 0; d4 < 8; d4++) {
            float4 v4;
            v4.x = of[d4*4+0] * inv; v4.y = of[d4*4+1] * inv;
            v4.z = of[d4*4+2] * inv; v4.w = of[d4*4+3] * inv;
            *(float4*)(op + d4 * 4) = v4;
        }
    }
}

// ------------------------------------------------- Residual + LayerNorm ----
// warp-per-row, float4, shfl-only (R15, known-good). 8 rows/block.
__global__ __launch_bounds__(256) void ln_kernel(
    const float* __restrict__ X, const float* __restrict__ Y,
    const float* __restrict__ g, const float* __restrict__ bta,
    float* __restrict__ Out)
{
    const int warp = threadIdx.x >> 5;
    const int lane = threadIdx.x & 31;
    const int r = blockIdx.x * 8 + warp;

    const float4* x4 = (const float4*)(X + (size_t)r * HH) + lane * 2;
    const float4* y4 = (const float4*)(Y + (size_t)r * HH) + lane * 2;
    float4 a0 = x4[0], a1 = x4[1];
    float4 b0 = y4[0], b1 = y4[1];
    float v[8];
    v[0] = a0.x + b0.x; v[1] = a0.y + b0.y; v[2] = a0.z + b0.z; v[3] = a0.w + b0.w;
    v[4] = a1.x + b1.x; v[5] = a1.y + b1.y; v[6] = a1.z + b1.z; v[7] = a1.w + b1.w;

    float s1 = 0.f, s2 = 0.f;
#pragma unroll
    for (int d = 0; d < 8; d++) { s1 += v[d]; s2 += v[d] * v[d]; }
#pragma unroll
    for (int o = 16; o; o >>= 1) {
        s1 += __shfl_xor_sync(0xffffffffu, s1, o);
        s2 += __shfl_xor_sync(0xffffffffu, s2, o);
    }
    float mean = s1 * (1.f / HH);
    float var  = s2 * (1.f / HH) - mean * mean;
    float rstd = rsqrtf(var + EPSLN);

    const float4* g4 = (const float4*)g + lane * 2;
    const float4* t4 = (const float4*)bta + lane * 2;
    float4 gg0 = g4[0], gg1 = g4[1];
    float4 tt0 = t4[0], tt1 = t4[1];
    float4 o0, o1;
    o0.x = (v[0] - mean) * rstd * gg0.x + tt0.x;
    o0.y = (v[1] - mean) * rstd * gg0.y + tt0.y;
    o0.z = (v[2] - mean) * rstd * gg0.z + tt0.z;
    o0.w = (v[3] - mean) * rstd * gg0.w + tt0.w;
    o1.x = (v[4] - mean) * rstd * gg1.x + tt1.x;
    o1.y = (v[5] - mean) * rstd * gg1.y + tt1.y;
    o1.z = (v[6] - mean) * rstd * gg1.z + tt1.z;
    o1.w = (v[7] - mean) * rstd * gg1.w + tt1.w;
    float4* out4 = (float4*)(Out + (size_t)r * HH) + lane * 2;
    out4[0] = o0;
    out4[1] = o1;
}

// ------------------------------------------------------------- launcher ----
extern "C" void kernel_launch(void* const* d_in, const int* in_sizes, int n_in,
                              void* d_out, int out_size)
{
    const float* inputs = (const float*)d_in[0];
    const float* Wq  = (const float*)d_in[1];
    const float* Wk  = (const float*)d_in[2];
    const float* Wv  = (const float*)d_in[3];
    const float* Wo  = (const float*)d_in[4];
    const float* bo  = (const float*)d_in[5];
    const float* W1  = (const float*)d_in[6];
    const float* b1  = (const float*)d_in[7];
    const float* W2  = (const float*)d_in[8];
    const float* b2  = (const float*)d_in[9];
    const float* ln1g = (const float*)d_in[10];
    const float* ln1b = (const float*)d_in[11];
    const float* ln2g = (const float*)d_in[12];
    const float* ln2b = (const float*)d_in[13];
    const float* Ek  = (const float*)d_in[14];
    const float* Ev  = (const float*)d_in[15];
    const int*   rel = (const int*)d_in[16];
    const int*   rmask = (const int*)d_in[17];
    float* out = (float*)d_out;

    float *qb, *kb, *vb, *ab, *yb, *xb, *fb;
    cudaGetSymbolAddress((void**)&qb, g_qb);
    cudaGetSymbolAddress((void**)&kb, g_kb);
    cudaGetSymbolAddress((void**)&vb, g_vb);
    cudaGetSymbolAddress((void**)&ab, g_ab);
    cudaGetSymbolAddress((void**)&yb, g_yb);
    cudaGetSymbolAddress((void**)&xb, g_xb);
    cudaGetSymbolAddress((void**)&fb, g_fb);

    cudaFuncSetAttribute(attn_kernel,
                         cudaFuncAttributeMaxDynamicSharedMemorySize,
                         ATTN_SMEM_BYTES);

    for (int l = 0; l < NLAYER; l++) {
        const float* x = (l == 0) ? inputs : xb;
        const size_t wHH = (size_t)l * HH * HH;
        const size_t wHF = (size_t)l * HH * FFD;

        gemm_qkv_kernel<<<dim3(HH/BN, ROWS/BM, 3), 256>>>(
            x, Wq + wHH, Wk + wHH, Wv + wHH, qb, kb, vb);

        attn_kernel<<<dim3(LL/TI, BB*2), 128, ATTN_SMEM_BYTES>>>(qb, kb, vb, Ek, Ev, rel, rmask, ab);

        gemm_kernel<<<dim3(HH/BN, ROWS/BM), 256>>>(ab, Wo + wHH, bo + l*HH, yb, HH, HH, 0);
        ln_kernel<<<ROWS/8, 256>>>(x, yb, ln1g + l*HH, ln1b + l*HH, xb);

        gemm_kernel<<<dim3(FFD/BN, ROWS/BM), 256>>>(xb, W1 + wHF, b1 + l*FFD, fb, FFD, HH, 1);
        gemm_kernel<<<dim3(HH/BN, ROWS/BM), 256>>>(fb, W2 + wHF, b2 + l*HH, yb, HH, FFD, 0);
        ln_kernel<<<ROWS/8, 256>>>(xb, yb, ln2g + l*HH, ln2b + l*HH, (l == NLAYER-1) ? out : xb);
    }
}